// round 6
// baseline (speedup 1.0000x reference)
#include <cuda_runtime.h>
#include <cuda_fp16.h>

// Problem dims (fixed for this problem instance)
#define B_  2048
#define T_  512
#define I_  58      // input features
#define H_  23      // hidden
#define G_  69      // 3*H gate rows
#define GP_ 72      // padded gate dim
#define KP_ 64      // padded K for tf32 mma (8 k-frags of 8)

// Scratch for x-projection, fp16: [B][T][GP_] (~151 MB, static device array — no allocs)
__device__ __half g_xg[(size_t)B_ * T_ * GP_];

// ---------------------------------------------------------------------------
// Helpers
// ---------------------------------------------------------------------------
__device__ __forceinline__ unsigned cvt_tf32(float f) {
    unsigned u;
    asm("cvt.rna.tf32.f32 %0, %1;" : "=r"(u) : "f"(f));
    return u;
}
__device__ __forceinline__ unsigned long long pack2(float lo, float hi) {
    unsigned long long r;
    asm("mov.b64 %0, {%1, %2};" : "=l"(r) : "f"(lo), "f"(hi));
    return r;
}
__device__ __forceinline__ void unpack2(unsigned long long v, float& lo, float& hi) {
    asm("mov.b64 {%0, %1}, %2;" : "=f"(lo), "=f"(hi) : "l"(v));
}
// Packed dual-FMA (Blackwell f32x2)
__device__ __forceinline__ unsigned long long ffma2(unsigned long long a,
                                                    unsigned long long b,
                                                    unsigned long long c) {
    unsigned long long d;
    asm("fma.rn.f32x2 %0, %1, %2, %3;" : "=l"(d) : "l"(a), "l"(b), "l"(c));
    return d;
}
__device__ __forceinline__ unsigned long long add2(unsigned long long a,
                                                   unsigned long long b) {
    unsigned long long d;
    asm("add.rn.f32x2 %0, %1, %2;" : "=l"(d) : "l"(a), "l"(b));
    return d;
}

// Accurate fast sigmoid/tanh via MUFU.EX2 + MUFU.RCP (~1e-7 rel err)
__device__ __forceinline__ float fast_sigmoid(float x) {
    float e, r;
    asm("ex2.approx.f32 %0, %1;" : "=f"(e) : "f"(x * -1.4426950408889634f));
    asm("rcp.approx.f32 %0, %1;" : "=f"(r) : "f"(e + 1.0f));
    return r;
}
__device__ __forceinline__ float fast_tanh(float x) {
    float e, r;
    asm("ex2.approx.f32 %0, %1;" : "=f"(e) : "f"(x * -2.8853900817779268f));
    asm("rcp.approx.f32 %0, %1;" : "=f"(r) : "f"(e + 1.0f));
    return fmaf(2.0f, r, -1.0f);
}

// ---------------------------------------------------------------------------
// Kernel 1: x-projection GEMM (tf32 mma.sync):
//   xg[b][t][g] = fp16( task[b][t]·W_ih^T + b_ih ),  row m = b*T + t (contiguous).
// ---------------------------------------------------------------------------
__global__ void __launch_bounds__(256, 2)
xproj_kernel(const float* __restrict__ task,
             const float* __restrict__ Wih,
             const float* __restrict__ bih)
{
    __shared__ unsigned Bsh[KP_][GP_];   // tf32 bits: Bsh[k][n] = Wih[n][k]
    __shared__ float    bias[GP_];

    const int tid = threadIdx.x;

    for (int idx = tid; idx < KP_ * GP_; idx += 256) {
        int k = idx / GP_, n = idx % GP_;
        float v = (k < I_ && n < G_) ? Wih[n * I_ + k] : 0.0f;
        Bsh[k][n] = cvt_tf32(v);
    }
    if (tid < GP_) bias[tid] = (tid < G_) ? bih[tid] : 0.0f;
    __syncthreads();

    const int warp = tid >> 5;
    const int lane = tid & 31;
    const int qr = lane >> 2;   // groupID (0..7)
    const int qc = lane & 3;    // tid-in-group (0..3)
    const int m_warp = blockIdx.x * 256 + warp * 32;

    float acc[2][9][4];
#pragma unroll
    for (int mt = 0; mt < 2; mt++)
#pragma unroll
        for (int nt = 0; nt < 9; nt++)
#pragma unroll
            for (int i = 0; i < 4; i++) acc[mt][nt][i] = 0.0f;

#pragma unroll
    for (int kf = 0; kf < 8; kf++) {
        const int k0 = kf * 8;
        unsigned bfr[9][2];
#pragma unroll
        for (int nt = 0; nt < 9; nt++) {
            bfr[nt][0] = Bsh[k0 + qc][nt * 8 + qr];
            bfr[nt][1] = Bsh[k0 + qc + 4][nt * 8 + qr];
        }
        const int c0 = k0 + qc;
        const int c1 = c0 + 4;
#pragma unroll
        for (int mt = 0; mt < 2; mt++) {
            const float* arow0 = task + (size_t)(m_warp + mt * 16 + qr) * I_;
            const float* arow1 = arow0 + (size_t)8 * I_;
            unsigned a0 = (c0 < I_) ? cvt_tf32(__ldg(arow0 + c0)) : 0u;
            unsigned a1 = (c0 < I_) ? cvt_tf32(__ldg(arow1 + c0)) : 0u;
            unsigned a2 = (c1 < I_) ? cvt_tf32(__ldg(arow0 + c1)) : 0u;
            unsigned a3 = (c1 < I_) ? cvt_tf32(__ldg(arow1 + c1)) : 0u;
#pragma unroll
            for (int nt = 0; nt < 9; nt++) {
                asm volatile(
                    "mma.sync.aligned.m16n8k8.row.col.f32.tf32.tf32.f32 "
                    "{%0,%1,%2,%3}, {%4,%5,%6,%7}, {%8,%9}, {%0,%1,%2,%3};"
                    : "+f"(acc[mt][nt][0]), "+f"(acc[mt][nt][1]),
                      "+f"(acc[mt][nt][2]), "+f"(acc[mt][nt][3])
                    : "r"(a0), "r"(a1), "r"(a2), "r"(a3),
                      "r"(bfr[nt][0]), "r"(bfr[nt][1]));
            }
        }
    }

    // Epilogue: bias add, convert to fp16, write contiguous 144B rows
#pragma unroll
    for (int mt = 0; mt < 2; mt++) {
#pragma unroll
        for (int half = 0; half < 2; half++) {
            const int m = m_warp + mt * 16 + qr + half * 8;
            __half* orow = g_xg + (size_t)m * GP_;
#pragma unroll
            for (int nt = 0; nt < 9; nt++) {
                const int n = nt * 8 + qc * 2;
                __half2 v = __floats2half2_rn(
                    acc[mt][nt][half * 2 + 0] + bias[n],
                    acc[mt][nt][half * 2 + 1] + bias[n + 1]);
                *reinterpret_cast<__half2*>(orow + n) = v;
            }
        }
    }
}

// ---------------------------------------------------------------------------
// Kernel 2: GRU scan, TWO batches per warp (1024 one-warp blocks).
//   Two independent dependency chains per warp hide the serial
//   sync->LDS->ffma2->MUFU latency; W_hh registers shared between batches.
// ---------------------------------------------------------------------------
__global__ void __launch_bounds__(32)
scan_kernel(const float* __restrict__ Whh,
            const float* __restrict__ bhh,
            const float* __restrict__ piw_g,
            const float* __restrict__ pib_g,
            float* __restrict__ out)
{
    const int lane = threadIdx.x;
    const bool act = lane < H_;
    const int l    = act ? lane : 0;
    const int b0   = blockIdx.x * 2;          // batches b0, b0+1

    __shared__ __align__(16) float hsh[2][2][24];   // [batch-slot][buf][unit]

    // Shared weights: W_hh rows for this lane as j-pairs (j=23 padded with 0)
    unsigned long long wr[12], wz[12], wn[12];
#pragma unroll
    for (int j = 0; j < 12; j++) {
        const int j0 = 2 * j, j1 = 2 * j + 1;
        float r1 = (j1 < H_) ? Whh[(size_t)l * H_ + j1] : 0.0f;
        float z1 = (j1 < H_) ? Whh[(size_t)(H_ + l) * H_ + j1] : 0.0f;
        float n1 = (j1 < H_) ? Whh[(size_t)(2 * H_ + l) * H_ + j1] : 0.0f;
        wr[j] = pack2(Whh[(size_t)l * H_ + j0], r1);
        wz[j] = pack2(Whh[(size_t)(H_ + l) * H_ + j0], z1);
        wn[j] = pack2(Whh[(size_t)(2 * H_ + l) * H_ + j0], n1);
    }
    const unsigned long long br0 = pack2(bhh[l], 0.0f);
    const unsigned long long bz0 = pack2(bhh[H_ + l], 0.0f);
    const unsigned long long bn0 = pack2(bhh[2 * H_ + l], 0.0f);
    const float piw = piw_g[l], pib = pib_g[l];

    // Per-batch state
    ulonglong2 h4[2][6];
    float hmine[2] = {0.0f, 0.0f};
    const __half* pf[2];
    float xr0[2], xz0[2], xn0[2], xr1[2], xz1[2], xn1[2];
    float* op[2];
#pragma unroll
    for (int u = 0; u < 2; u++) {
#pragma unroll
        for (int j = 0; j < 6; j++) { h4[u][j].x = 0ull; h4[u][j].y = 0ull; }
        if (lane < 24) { hsh[u][0][lane] = 0.0f; hsh[u][1][lane] = 0.0f; }
        const __half* xb = g_xg + (size_t)(b0 + u) * T_ * GP_;
        xr0[u] = __half2float(xb[l]);
        xz0[u] = __half2float(xb[H_ + l]);
        xn0[u] = __half2float(xb[2 * H_ + l]);
        xr1[u] = __half2float(xb[GP_ + l]);
        xz1[u] = __half2float(xb[GP_ + H_ + l]);
        xn1[u] = __half2float(xb[GP_ + 2 * H_ + l]);
        pf[u] = xb + 2 * GP_;
        op[u] = out + (size_t)(b0 + u) * T_ * H_ + lane;
    }
    __syncwarp();

    for (int t = 0; t < T_; t++) {
        const int pb = t & 1;
        float hnew[2];
#pragma unroll
        for (int u = 0; u < 2; u++) {
            const float xr = xr0[u], xz = xz0[u], xn = xn0[u];
            xr0[u] = xr1[u]; xz0[u] = xz1[u]; xn0[u] = xn1[u];
            xr1[u] = __half2float(pf[u][l]);
            xz1[u] = __half2float(pf[u][H_ + l]);
            xn1[u] = __half2float(pf[u][2 * H_ + l]);
            if (t + 3 < T_) pf[u] += GP_;

            // hg = W_hh · h + b_hh  (two 6-deep packed chains per gate)
            unsigned long long ar0 = br0, ar1 = 0ull;
            unsigned long long az0 = bz0, az1 = 0ull;
            unsigned long long an0 = bn0, an1 = 0ull;
#pragma unroll
            for (int jj = 0; jj < 3; jj++) {
                ar0 = ffma2(wr[2 * jj],     h4[u][jj].x, ar0);
                az0 = ffma2(wz[2 * jj],     h4[u][jj].x, az0);
                an0 = ffma2(wn[2 * jj],     h4[u][jj].x, an0);
                ar0 = ffma2(wr[2 * jj + 1], h4[u][jj].y, ar0);
                az0 = ffma2(wz[2 * jj + 1], h4[u][jj].y, az0);
                an0 = ffma2(wn[2 * jj + 1], h4[u][jj].y, an0);
            }
#pragma unroll
            for (int jj = 3; jj < 6; jj++) {
                ar1 = ffma2(wr[2 * jj],     h4[u][jj].x, ar1);
                az1 = ffma2(wz[2 * jj],     h4[u][jj].x, az1);
                an1 = ffma2(wn[2 * jj],     h4[u][jj].x, an1);
                ar1 = ffma2(wr[2 * jj + 1], h4[u][jj].y, ar1);
                az1 = ffma2(wz[2 * jj + 1], h4[u][jj].y, az1);
                an1 = ffma2(wn[2 * jj + 1], h4[u][jj].y, an1);
            }
            float hrx, hry, hzx, hzy, hnx, hny;
            unpack2(add2(ar0, ar1), hrx, hry);
            unpack2(add2(az0, az1), hzx, hzy);
            unpack2(add2(an0, an1), hnx, hny);

            const float r = fast_sigmoid(xr + (hrx + hry));
            const float z = fast_sigmoid(xz + (hzx + hzy));
            const float n = fast_tanh(fmaf(r, hnx + hny, xn));
            hnew[u] = fmaf(z, hmine[u] - n, n);    // (1-z)*n + z*h

            if (act) *op[u] = fmaf(piw, hnew[u], pib);
            op[u] += H_;
            hmine[u] = hnew[u];
        }

        // Replicate h for both batches: writes, ONE syncwarp, reads.
        // Next step's syncwarp orders these reads before the (t+2) overwrite.
        if (act) { hsh[0][pb][lane] = hnew[0]; hsh[1][pb][lane] = hnew[1]; }
        __syncwarp();
#pragma unroll
        for (int u = 0; u < 2; u++)
#pragma unroll
            for (int j = 0; j < 6; j++)
                h4[u][j] = *reinterpret_cast<const ulonglong2*>(&hsh[u][pb][4 * j]);
    }

    // hidden = hT
    if (act) {
        out[(size_t)B_ * T_ * H_ + (size_t)b0 * H_ + lane]       = hmine[0];
        out[(size_t)B_ * T_ * H_ + (size_t)(b0 + 1) * H_ + lane] = hmine[1];
    }
}

// ---------------------------------------------------------------------------
extern "C" void kernel_launch(void* const* d_in, const int* in_sizes, int n_in,
                              void* d_out, int out_size)
{
    const float* task = (const float*)d_in[0];   // (2048, 512, 58)
    const float* Wih  = (const float*)d_in[1];   // (69, 58)
    const float* Whh  = (const float*)d_in[2];   // (69, 23)
    const float* bih  = (const float*)d_in[3];   // (69,)
    const float* bhh  = (const float*)d_in[4];   // (69,)
    const float* piw  = (const float*)d_in[5];   // (23,)
    const float* pib  = (const float*)d_in[6];   // (23,)
    float* out = (float*)d_out;                  // action_pred (2048,512,23) ++ hidden (1,2048,23)

    xproj_kernel<<<(B_ * T_) / 256, 256>>>(task, Wih, bih);
    scan_kernel<<<B_ / 2, 32>>>(Whh, bhh, piw, pib, out);
}

// round 10
// speedup vs baseline: 1.1272x; 1.1272x over previous
#include <cuda_runtime.h>
#include <cuda_fp16.h>

// Problem dims (fixed for this problem instance)
#define B_  2048
#define T_  512
#define I_  58      // input features
#define H_  23      // hidden
#define G_  69      // 3*H gate rows
#define GP_ 72      // padded gate dim
#define KP_ 64      // padded K for fp16 mma (4 k-frags of 16)
#define MT_ 256     // rows per xproj block

// Scratch for x-projection, fp16: [B][T][GP_] (~151 MB, static device array — no allocs)
__device__ __half g_xg[(size_t)B_ * T_ * GP_];

// ---------------------------------------------------------------------------
// Helpers
// ---------------------------------------------------------------------------
__device__ __forceinline__ unsigned long long pack2(float lo, float hi) {
    unsigned long long r;
    asm("mov.b64 %0, {%1, %2};" : "=l"(r) : "f"(lo), "f"(hi));
    return r;
}
__device__ __forceinline__ void unpack2(unsigned long long v, float& lo, float& hi) {
    asm("mov.b64 {%0, %1}, %2;" : "=f"(lo), "=f"(hi) : "l"(v));
}
// Packed dual-FMA (Blackwell f32x2)
__device__ __forceinline__ unsigned long long ffma2(unsigned long long a,
                                                    unsigned long long b,
                                                    unsigned long long c) {
    unsigned long long d;
    asm("fma.rn.f32x2 %0, %1, %2, %3;" : "=l"(d) : "l"(a), "l"(b), "l"(c));
    return d;
}
__device__ __forceinline__ unsigned long long add2(unsigned long long a,
                                                   unsigned long long b) {
    unsigned long long d;
    asm("add.rn.f32x2 %0, %1, %2;" : "=l"(d) : "l"(a), "l"(b));
    return d;
}
// Single-op MUFU tanh (sm_75+), ~5e-4 max abs err — recurrence damps it (measured)
__device__ __forceinline__ float mtanh(float x) {
    float r;
    asm("tanh.approx.f32 %0, %1;" : "=f"(r) : "f"(x));
    return r;
}

// ---------------------------------------------------------------------------
// Kernel 1: x-projection GEMM, fp16 HMMA m16n8k16 (full-rate; fp16 mantissa ==
//   tf32 mantissa so accuracy unchanged). Task tile staged via float4 loads
//   into fp16 smem; W/bias in smem. xg[b][t][g] fp16, row m = b*T + t.
// ---------------------------------------------------------------------------
__global__ void __launch_bounds__(256)
xproj_kernel(const float* __restrict__ task,
             const float* __restrict__ Wih,
             const float* __restrict__ bih)
{
    __shared__ __half Ash[MT_][GP_];   // [row][k] fp16, stride 72 (conflict-free)
    __shared__ __half Wsh[GP_][GP_];   // [n][k]  fp16 (col-major B for .col)
    __shared__ float  bias[GP_];

    const int tid  = threadIdx.x;
    const int m0   = blockIdx.x * MT_;

    // Zero both staging arrays (covers K/N padding)
    {
        uint4 z = {0u, 0u, 0u, 0u};
        uint4* pa = reinterpret_cast<uint4*>(&Ash[0][0]);
        uint4* pw = reinterpret_cast<uint4*>(&Wsh[0][0]);
        for (int i = tid; i < (MT_ * GP_ * 2) / 16; i += 256) pa[i] = z;
        for (int i = tid; i < (GP_ * GP_ * 2) / 16; i += 256) pw[i] = z;
    }
    if (tid < GP_) bias[tid] = (tid < G_) ? bih[tid] : 0.0f;
    __syncthreads();

    // Stage task tile: 256 rows x 58 fp32, contiguous -> float4 loads
    {
        const float4* t4 = reinterpret_cast<const float4*>(task + (size_t)m0 * I_);
        const int n4 = (MT_ * I_) / 4;   // 3712
        for (int i = tid; i < n4; i += 256) {
            float4 v = t4[i];
            int base = i * 4;
#pragma unroll
            for (int j = 0; j < 4; j++) {
                int idx = base + j;
                int r = idx / I_;
                int c = idx - r * I_;
                float f = (j == 0) ? v.x : (j == 1) ? v.y : (j == 2) ? v.z : v.w;
                Ash[r][c] = __float2half_rn(f);
            }
        }
        // Stage W: Wih row-major [n][k] maps directly
        for (int i = tid; i < G_ * I_; i += 256) {
            int n = i / I_;
            int k = i - n * I_;
            Wsh[n][k] = __float2half_rn(Wih[i]);
        }
    }
    __syncthreads();

    const int warp = tid >> 5;
    const int lane = tid & 31;
    const int qr = lane >> 2;   // groupID (0..7)
    const int qc = lane & 3;    // tid-in-group (0..3)
    const int rw = warp * 32;   // warp's row base within tile

    float acc[2][9][4];
#pragma unroll
    for (int mt = 0; mt < 2; mt++)
#pragma unroll
        for (int nt = 0; nt < 9; nt++)
#pragma unroll
            for (int i = 0; i < 4; i++) acc[mt][nt][i] = 0.0f;

#pragma unroll
    for (int kf = 0; kf < 4; kf++) {
        const int k0 = kf * 16;
        unsigned a[2][4];
#pragma unroll
        for (int mt = 0; mt < 2; mt++) {
            const int r0 = rw + mt * 16 + qr;
            a[mt][0] = *reinterpret_cast<const unsigned*>(&Ash[r0][k0 + qc * 2]);
            a[mt][1] = *reinterpret_cast<const unsigned*>(&Ash[r0 + 8][k0 + qc * 2]);
            a[mt][2] = *reinterpret_cast<const unsigned*>(&Ash[r0][k0 + 8 + qc * 2]);
            a[mt][3] = *reinterpret_cast<const unsigned*>(&Ash[r0 + 8][k0 + 8 + qc * 2]);
        }
#pragma unroll
        for (int nt = 0; nt < 9; nt++) {
            unsigned b0 = *reinterpret_cast<const unsigned*>(&Wsh[nt * 8 + qr][k0 + qc * 2]);
            unsigned b1 = *reinterpret_cast<const unsigned*>(&Wsh[nt * 8 + qr][k0 + 8 + qc * 2]);
#pragma unroll
            for (int mt = 0; mt < 2; mt++) {
                asm volatile(
                    "mma.sync.aligned.m16n8k16.row.col.f32.f16.f16.f32 "
                    "{%0,%1,%2,%3}, {%4,%5,%6,%7}, {%8,%9}, {%0,%1,%2,%3};"
                    : "+f"(acc[mt][nt][0]), "+f"(acc[mt][nt][1]),
                      "+f"(acc[mt][nt][2]), "+f"(acc[mt][nt][3])
                    : "r"(a[mt][0]), "r"(a[mt][1]), "r"(a[mt][2]), "r"(a[mt][3]),
                      "r"(b0), "r"(b1));
            }
        }
    }

    // Epilogue: bias add, fp16 convert, contiguous 144B rows
#pragma unroll
    for (int mt = 0; mt < 2; mt++) {
#pragma unroll
        for (int half = 0; half < 2; half++) {
            const int m = m0 + rw + mt * 16 + qr + half * 8;
            __half* orow = g_xg + (size_t)m * GP_;
#pragma unroll
            for (int nt = 0; nt < 9; nt++) {
                const int n = nt * 8 + qc * 2;
                __half2 v = __floats2half2_rn(
                    acc[mt][nt][half * 2 + 0] + bias[n],
                    acc[mt][nt][half * 2 + 1] + bias[n + 1]);
                *reinterpret_cast<__half2*>(orow + n) = v;
            }
        }
    }
}

// ---------------------------------------------------------------------------
// Kernel 2: GRU scan. One warp per batch (2048 one-warp blocks — max warps;
//   R6 falsified the ILP variant). Lane l<23 owns unit l; W_hh in registers
//   as f32x2 pairs; h via double-buffered smem, ONE syncwarp/step.
//   Activations via single-op MUFU tanh; z folded into the hnew fma.
// ---------------------------------------------------------------------------
__global__ void __launch_bounds__(32)
scan_kernel(const float* __restrict__ Whh,
            const float* __restrict__ bhh,
            const float* __restrict__ piw_g,
            const float* __restrict__ pib_g,
            float* __restrict__ out)
{
    const int lane  = threadIdx.x;
    const int batch = blockIdx.x;
    const bool act  = lane < H_;
    const int l     = act ? lane : 0;

    __shared__ __align__(16) float hsh[2][24];   // double-buffered h (pad j=23)

    // W_hh rows for this lane as j-pairs (j=23 padded with 0)
    unsigned long long wr[12], wz[12], wn[12];
#pragma unroll
    for (int j = 0; j < 12; j++) {
        const int j0 = 2 * j, j1 = 2 * j + 1;
        float r1 = (j1 < H_) ? Whh[(size_t)l * H_ + j1] : 0.0f;
        float z1 = (j1 < H_) ? Whh[(size_t)(H_ + l) * H_ + j1] : 0.0f;
        float n1 = (j1 < H_) ? Whh[(size_t)(2 * H_ + l) * H_ + j1] : 0.0f;
        wr[j] = pack2(Whh[(size_t)l * H_ + j0], r1);
        wz[j] = pack2(Whh[(size_t)(H_ + l) * H_ + j0], z1);
        wn[j] = pack2(Whh[(size_t)(2 * H_ + l) * H_ + j0], n1);
    }
    const unsigned long long br0 = pack2(bhh[l], 0.0f);
    const unsigned long long bz0 = pack2(bhh[H_ + l], 0.0f);
    const unsigned long long bn0 = pack2(bhh[2 * H_ + l], 0.0f);
    const float piw = piw_g[l], pib = pib_g[l];

    ulonglong2 h4[6];      // 24 h values as 6x (f32x2, f32x2)
#pragma unroll
    for (int j = 0; j < 6; j++) { h4[j].x = 0ull; h4[j].y = 0ull; }
    float hmine = 0.0f;
    if (lane < 24) { hsh[0][lane] = 0.0f; hsh[1][lane] = 0.0f; }
    __syncwarp();

    const __half* xb = g_xg + (size_t)batch * T_ * GP_;
    float*        op = out + (size_t)batch * T_ * H_ + lane;

    // Prefetch pipeline, distance 2
    float xr0 = __half2float(xb[l]);
    float xz0 = __half2float(xb[H_ + l]);
    float xn0 = __half2float(xb[2 * H_ + l]);
    float xr1 = __half2float(xb[GP_ + l]);
    float xz1 = __half2float(xb[GP_ + H_ + l]);
    float xn1 = __half2float(xb[GP_ + 2 * H_ + l]);
    const __half* pf = xb + 2 * GP_;

    for (int t = 0; t < T_; t++) {
        const float xr = xr0, xz = xz0, xn = xn0;
        xr0 = xr1; xz0 = xz1; xn0 = xn1;
        xr1 = __half2float(pf[l]);
        xz1 = __half2float(pf[H_ + l]);
        xn1 = __half2float(pf[2 * H_ + l]);
        if (t + 3 < T_) pf += GP_;

        // hg = W_hh · h + b_hh  (two 6-deep packed chains per gate)
        unsigned long long ar0 = br0, ar1 = 0ull;
        unsigned long long az0 = bz0, az1 = 0ull;
        unsigned long long an0 = bn0, an1 = 0ull;
#pragma unroll
        for (int jj = 0; jj < 3; jj++) {
            ar0 = ffma2(wr[2 * jj],     h4[jj].x, ar0);
            az0 = ffma2(wz[2 * jj],     h4[jj].x, az0);
            an0 = ffma2(wn[2 * jj],     h4[jj].x, an0);
            ar0 = ffma2(wr[2 * jj + 1], h4[jj].y, ar0);
            az0 = ffma2(wz[2 * jj + 1], h4[jj].y, az0);
            an0 = ffma2(wn[2 * jj + 1], h4[jj].y, an0);
        }
#pragma unroll
        for (int jj = 3; jj < 6; jj++) {
            ar1 = ffma2(wr[2 * jj],     h4[jj].x, ar1);
            az1 = ffma2(wz[2 * jj],     h4[jj].x, az1);
            an1 = ffma2(wn[2 * jj],     h4[jj].x, an1);
            ar1 = ffma2(wr[2 * jj + 1], h4[jj].y, ar1);
            az1 = ffma2(wz[2 * jj + 1], h4[jj].y, az1);
            an1 = ffma2(wn[2 * jj + 1], h4[jj].y, an1);
        }
        float hrx, hry, hzx, hzy, hnx, hny;
        unpack2(add2(ar0, ar1), hrx, hry);
        unpack2(add2(az0, az1), hzx, hzy);
        unpack2(add2(an0, an1), hnx, hny);

        // r = sigmoid(xr+hr) = 0.5*tanh(0.5*(xr+hr)) + 0.5   (MUFU)
        const float r  = fmaf(0.5f, mtanh(0.5f * (xr + (hrx + hry))), 0.5f);
        // tz = tanh(0.5*(xz+hz));  z = 0.5*tz + 0.5 folded below
        const float tz = mtanh(0.5f * (xz + (hzx + hzy)));
        const float n  = mtanh(fmaf(r, hnx + hny, xn));
        // hnew = (1-z)n + zh = 0.5*(h+n) + 0.5*tz*(h-n)
        const float hnew = fmaf(0.5f * tz, hmine - n, 0.5f * (hmine + n));

        if (act) *op = fmaf(piw, hnew, pib);
        op += H_;
        hmine = hnew;

        // Replicate h: write buf (t&1), one syncwarp, read buf (t&1).
        const int pb = t & 1;
        if (act) hsh[pb][lane] = hnew;
        __syncwarp();
#pragma unroll
        for (int j = 0; j < 6; j++)
            h4[j] = *reinterpret_cast<const ulonglong2*>(&hsh[pb][4 * j]);
    }

    // hidden = hT
    if (act)
        out[(size_t)B_ * T_ * H_ + (size_t)batch * H_ + lane] = hmine;
}

// ---------------------------------------------------------------------------
extern "C" void kernel_launch(void* const* d_in, const int* in_sizes, int n_in,
                              void* d_out, int out_size)
{
    const float* task = (const float*)d_in[0];   // (2048, 512, 58)
    const float* Wih  = (const float*)d_in[1];   // (69, 58)
    const float* Whh  = (const float*)d_in[2];   // (69, 23)
    const float* bih  = (const float*)d_in[3];   // (69,)
    const float* bhh  = (const float*)d_in[4];   // (69,)
    const float* piw  = (const float*)d_in[5];   // (23,)
    const float* pib  = (const float*)d_in[6];   // (23,)
    float* out = (float*)d_out;                  // action_pred (2048,512,23) ++ hidden (1,2048,23)

    xproj_kernel<<<(B_ * T_) / MT_, 256>>>(task, Wih, bih);
    scan_kernel<<<B_, 32>>>(Whh, bhh, piw, pib, out);
}

// round 11
// speedup vs baseline: 1.2898x; 1.1443x over previous
#include <cuda_runtime.h>
#include <cuda_fp16.h>

// Problem dims (fixed for this problem instance)
#define B_  2048
#define T_  512
#define I_  58      // input features
#define H_  23      // hidden
#define G_  69      // 3*H gate rows
#define GP_ 72      // padded gate dim
#define KP_ 64      // padded K for tf32 mma (8 k-frags of 8)

// Scratch for x-projection, fp16: [B][T][GP_] (~151 MB, static device array — no allocs)
__device__ __half g_xg[(size_t)B_ * T_ * GP_];

// ---------------------------------------------------------------------------
// Helpers
// ---------------------------------------------------------------------------
__device__ __forceinline__ unsigned cvt_tf32(float f) {
    unsigned u;
    asm("cvt.rna.tf32.f32 %0, %1;" : "=r"(u) : "f"(f));
    return u;
}
__device__ __forceinline__ unsigned long long pack2(float lo, float hi) {
    unsigned long long r;
    asm("mov.b64 %0, {%1, %2};" : "=l"(r) : "f"(lo), "f"(hi));
    return r;
}
__device__ __forceinline__ void unpack2(unsigned long long v, float& lo, float& hi) {
    asm("mov.b64 {%0, %1}, %2;" : "=f"(lo), "=f"(hi) : "l"(v));
}
// Packed dual-FMA (Blackwell f32x2)
__device__ __forceinline__ unsigned long long ffma2(unsigned long long a,
                                                    unsigned long long b,
                                                    unsigned long long c) {
    unsigned long long d;
    asm("fma.rn.f32x2 %0, %1, %2, %3;" : "=l"(d) : "l"(a), "l"(b), "l"(c));
    return d;
}
__device__ __forceinline__ unsigned long long add2(unsigned long long a,
                                                   unsigned long long b) {
    unsigned long long d;
    asm("add.rn.f32x2 %0, %1, %2;" : "=l"(d) : "l"(a), "l"(b));
    return d;
}
// Single-op MUFU tanh (sm_75+), ~5e-4 max abs err — recurrence damps it (measured)
__device__ __forceinline__ float mtanh(float x) {
    float r;
    asm("tanh.approx.f32 %0, %1;" : "=f"(r) : "f"(x));
    return r;
}

// ---------------------------------------------------------------------------
// Kernel 1: x-projection GEMM (tf32 mma.sync — measured 152 µs config):
//   xg[b][t][g] = fp16( task[b][t]·W_ih^T + b_ih ),  row m = b*T + t (contiguous).
// ---------------------------------------------------------------------------
__global__ void __launch_bounds__(256, 2)
xproj_kernel(const float* __restrict__ task,
             const float* __restrict__ Wih,
             const float* __restrict__ bih)
{
    __shared__ unsigned Bsh[KP_][GP_];   // tf32 bits: Bsh[k][n] = Wih[n][k]
    __shared__ float    bias[GP_];

    const int tid = threadIdx.x;

    for (int idx = tid; idx < KP_ * GP_; idx += 256) {
        int k = idx / GP_, n = idx % GP_;
        float v = (k < I_ && n < G_) ? Wih[n * I_ + k] : 0.0f;
        Bsh[k][n] = cvt_tf32(v);
    }
    if (tid < GP_) bias[tid] = (tid < G_) ? bih[tid] : 0.0f;
    __syncthreads();

    const int warp = tid >> 5;
    const int lane = tid & 31;
    const int qr = lane >> 2;   // groupID (0..7)
    const int qc = lane & 3;    // tid-in-group (0..3)
    const int m_warp = blockIdx.x * 256 + warp * 32;

    float acc[2][9][4];
#pragma unroll
    for (int mt = 0; mt < 2; mt++)
#pragma unroll
        for (int nt = 0; nt < 9; nt++)
#pragma unroll
            for (int i = 0; i < 4; i++) acc[mt][nt][i] = 0.0f;

#pragma unroll
    for (int kf = 0; kf < 8; kf++) {
        const int k0 = kf * 8;
        unsigned bfr[9][2];
#pragma unroll
        for (int nt = 0; nt < 9; nt++) {
            bfr[nt][0] = Bsh[k0 + qc][nt * 8 + qr];
            bfr[nt][1] = Bsh[k0 + qc + 4][nt * 8 + qr];
        }
        const int c0 = k0 + qc;
        const int c1 = c0 + 4;
#pragma unroll
        for (int mt = 0; mt < 2; mt++) {
            const float* arow0 = task + (size_t)(m_warp + mt * 16 + qr) * I_;
            const float* arow1 = arow0 + (size_t)8 * I_;
            unsigned a0 = (c0 < I_) ? cvt_tf32(__ldg(arow0 + c0)) : 0u;
            unsigned a1 = (c0 < I_) ? cvt_tf32(__ldg(arow1 + c0)) : 0u;
            unsigned a2 = (c1 < I_) ? cvt_tf32(__ldg(arow0 + c1)) : 0u;
            unsigned a3 = (c1 < I_) ? cvt_tf32(__ldg(arow1 + c1)) : 0u;
#pragma unroll
            for (int nt = 0; nt < 9; nt++) {
                asm volatile(
                    "mma.sync.aligned.m16n8k8.row.col.f32.tf32.tf32.f32 "
                    "{%0,%1,%2,%3}, {%4,%5,%6,%7}, {%8,%9}, {%0,%1,%2,%3};"
                    : "+f"(acc[mt][nt][0]), "+f"(acc[mt][nt][1]),
                      "+f"(acc[mt][nt][2]), "+f"(acc[mt][nt][3])
                    : "r"(a0), "r"(a1), "r"(a2), "r"(a3),
                      "r"(bfr[nt][0]), "r"(bfr[nt][1]));
            }
        }
    }

    // Epilogue: bias add, convert to fp16, write contiguous 144B rows
#pragma unroll
    for (int mt = 0; mt < 2; mt++) {
#pragma unroll
        for (int half = 0; half < 2; half++) {
            const int m = m_warp + mt * 16 + qr + half * 8;
            __half* orow = g_xg + (size_t)m * GP_;
#pragma unroll
            for (int nt = 0; nt < 9; nt++) {
                const int n = nt * 8 + qc * 2;
                __half2 v = __floats2half2_rn(
                    acc[mt][nt][half * 2 + 0] + bias[n],
                    acc[mt][nt][half * 2 + 1] + bias[n + 1]);
                *reinterpret_cast<__half2*>(orow + n) = v;
            }
        }
    }
}

// ---------------------------------------------------------------------------
// Kernel 2: GRU scan — MEASURED 189 µs config, unchanged.
//   One warp per batch (2048 one-warp blocks). Lane l<23 owns unit l; W_hh in
//   registers as f32x2 pairs; h via double-buffered smem, ONE syncwarp/step.
//   Activations via single-op MUFU tanh; z folded into the hnew fma.
// ---------------------------------------------------------------------------
__global__ void __launch_bounds__(32)
scan_kernel(const float* __restrict__ Whh,
            const float* __restrict__ bhh,
            const float* __restrict__ piw_g,
            const float* __restrict__ pib_g,
            float* __restrict__ out)
{
    const int lane  = threadIdx.x;
    const int batch = blockIdx.x;
    const bool act  = lane < H_;
    const int l     = act ? lane : 0;

    __shared__ __align__(16) float hsh[2][24];   // double-buffered h (pad j=23)

    // W_hh rows for this lane as j-pairs (j=23 padded with 0)
    unsigned long long wr[12], wz[12], wn[12];
#pragma unroll
    for (int j = 0; j < 12; j++) {
        const int j0 = 2 * j, j1 = 2 * j + 1;
        float r1 = (j1 < H_) ? Whh[(size_t)l * H_ + j1] : 0.0f;
        float z1 = (j1 < H_) ? Whh[(size_t)(H_ + l) * H_ + j1] : 0.0f;
        float n1 = (j1 < H_) ? Whh[(size_t)(2 * H_ + l) * H_ + j1] : 0.0f;
        wr[j] = pack2(Whh[(size_t)l * H_ + j0], r1);
        wz[j] = pack2(Whh[(size_t)(H_ + l) * H_ + j0], z1);
        wn[j] = pack2(Whh[(size_t)(2 * H_ + l) * H_ + j0], n1);
    }
    const unsigned long long br0 = pack2(bhh[l], 0.0f);
    const unsigned long long bz0 = pack2(bhh[H_ + l], 0.0f);
    const unsigned long long bn0 = pack2(bhh[2 * H_ + l], 0.0f);
    const float piw = piw_g[l], pib = pib_g[l];

    ulonglong2 h4[6];      // 24 h values as 6x (f32x2, f32x2)
#pragma unroll
    for (int j = 0; j < 6; j++) { h4[j].x = 0ull; h4[j].y = 0ull; }
    float hmine = 0.0f;
    if (lane < 24) { hsh[0][lane] = 0.0f; hsh[1][lane] = 0.0f; }
    __syncwarp();

    const __half* xb = g_xg + (size_t)batch * T_ * GP_;
    float*        op = out + (size_t)batch * T_ * H_ + lane;

    // Prefetch pipeline, distance 2
    float xr0 = __half2float(xb[l]);
    float xz0 = __half2float(xb[H_ + l]);
    float xn0 = __half2float(xb[2 * H_ + l]);
    float xr1 = __half2float(xb[GP_ + l]);
    float xz1 = __half2float(xb[GP_ + H_ + l]);
    float xn1 = __half2float(xb[GP_ + 2 * H_ + l]);
    const __half* pf = xb + 2 * GP_;

    for (int t = 0; t < T_; t++) {
        const float xr = xr0, xz = xz0, xn = xn0;
        xr0 = xr1; xz0 = xz1; xn0 = xn1;
        xr1 = __half2float(pf[l]);
        xz1 = __half2float(pf[H_ + l]);
        xn1 = __half2float(pf[2 * H_ + l]);
        if (t + 3 < T_) pf += GP_;

        // hg = W_hh · h + b_hh  (two 6-deep packed chains per gate)
        unsigned long long ar0 = br0, ar1 = 0ull;
        unsigned long long az0 = bz0, az1 = 0ull;
        unsigned long long an0 = bn0, an1 = 0ull;
#pragma unroll
        for (int jj = 0; jj < 3; jj++) {
            ar0 = ffma2(wr[2 * jj],     h4[jj].x, ar0);
            az0 = ffma2(wz[2 * jj],     h4[jj].x, az0);
            an0 = ffma2(wn[2 * jj],     h4[jj].x, an0);
            ar0 = ffma2(wr[2 * jj + 1], h4[jj].y, ar0);
            az0 = ffma2(wz[2 * jj + 1], h4[jj].y, az0);
            an0 = ffma2(wn[2 * jj + 1], h4[jj].y, an0);
        }
#pragma unroll
        for (int jj = 3; jj < 6; jj++) {
            ar1 = ffma2(wr[2 * jj],     h4[jj].x, ar1);
            az1 = ffma2(wz[2 * jj],     h4[jj].x, az1);
            an1 = ffma2(wn[2 * jj],     h4[jj].x, an1);
            ar1 = ffma2(wr[2 * jj + 1], h4[jj].y, ar1);
            az1 = ffma2(wz[2 * jj + 1], h4[jj].y, az1);
            an1 = ffma2(wn[2 * jj + 1], h4[jj].y, an1);
        }
        float hrx, hry, hzx, hzy, hnx, hny;
        unpack2(add2(ar0, ar1), hrx, hry);
        unpack2(add2(az0, az1), hzx, hzy);
        unpack2(add2(an0, an1), hnx, hny);

        // r = sigmoid(xr+hr) = 0.5*tanh(0.5*(xr+hr)) + 0.5   (MUFU)
        const float r  = fmaf(0.5f, mtanh(0.5f * (xr + (hrx + hry))), 0.5f);
        // tz = tanh(0.5*(xz+hz));  z = 0.5*tz + 0.5 folded below
        const float tz = mtanh(0.5f * (xz + (hzx + hzy)));
        const float n  = mtanh(fmaf(r, hnx + hny, xn));
        // hnew = (1-z)n + zh = 0.5*(h+n) + 0.5*tz*(h-n)
        const float hnew = fmaf(0.5f * tz, hmine - n, 0.5f * (hmine + n));

        if (act) *op = fmaf(piw, hnew, pib);
        op += H_;
        hmine = hnew;

        // Replicate h: write buf (t&1), one syncwarp, read buf (t&1).
        const int pb = t & 1;
        if (act) hsh[pb][lane] = hnew;
        __syncwarp();
#pragma unroll
        for (int j = 0; j < 6; j++)
            h4[j] = *reinterpret_cast<const ulonglong2*>(&hsh[pb][4 * j]);
    }

    // hidden = hT
    if (act)
        out[(size_t)B_ * T_ * H_ + (size_t)batch * H_ + lane] = hmine;
}

// ---------------------------------------------------------------------------
extern "C" void kernel_launch(void* const* d_in, const int* in_sizes, int n_in,
                              void* d_out, int out_size)
{
    const float* task = (const float*)d_in[0];   // (2048, 512, 58)
    const float* Wih  = (const float*)d_in[1];   // (69, 58)
    const float* Whh  = (const float*)d_in[2];   // (69, 23)
    const float* bih  = (const float*)d_in[3];   // (69,)
    const float* bhh  = (const float*)d_in[4];   // (69,)
    const float* piw  = (const float*)d_in[5];   // (23,)
    const float* pib  = (const float*)d_in[6];   // (23,)
    float* out = (float*)d_out;                  // action_pred (2048,512,23) ++ hidden (1,2048,23)

    xproj_kernel<<<(B_ * T_) / 256, 256>>>(task, Wih, bih);
    scan_kernel<<<B_, 32>>>(Whh, bhh, piw, pib, out);
}